// round 15
// baseline (speedup 1.0000x reference)
#include <cuda_runtime.h>
#include <cuda_fp16.h>
#include <math.h>
#include <mma.h>
#include <stdint.h>

using namespace nvcuda;

#define BB 32
#define TT 1024
#define DD 512
#define MM (BB * TT)
#define NPERS 444   // 148 SMs x 3 CTAs

// Scratch (__device__ globals; no allocations allowed)
__device__ float  g_brep[16 * DD];        // replicated Wo bias (final linear)
__device__ float  g_brep3[16 * 3 * DD];   // replicated [0 | 0 | bq] (fused linear)
__device__ __half g_Kh[MM * DD];
__device__ __half g_Vh[MM * DD];
__device__ __half g_Qh[MM * DD];
__device__ __half g_xh[MM * DD];
__device__ __half g_W3h[3 * DD * DD];
__device__ __half g_Woh[DD * DD];
__device__ __half g_expwh[TT * TT];
__device__ __half g_EKh[MM * DD];
__device__ __half g_EKVh[MM * DD];
__device__ __half g_Yth[MM * DD];

__device__ __forceinline__ uint32_t smem_u32(const void* p) {
    uint32_t a;
    asm("{ .reg .u64 t; cvta.to.shared.u64 t, %1; cvt.u32.u64 %0, t; }"
        : "=r"(a) : "l"(p));
    return a;
}

#define CP16(dst, src) \
    asm volatile("cp.async.cg.shared.global [%0], [%1], 16;" \
        :: "r"(smem_u32(dst)), "l"((const void*)(src)) : "memory")
#define CP_COMMIT() asm volatile("cp.async.commit_group;" ::: "memory")
#define CP_WAIT0()  asm volatile("cp.async.wait_group 0;" ::: "memory")

// ===========================================================================
// Persistent linear NT GEMM (fp16 WMMA, fp32 acc, K-chunk 64, double buffer,
// cross-tile prefetch). Block tile 128x128, 128 threads, warp tile 64x64.
// grid = NPERS; tiles decoded as (m, n) from linear index.
// Fused mode (outf==null): convert acc to half, route to Kh/Vh/Qh by n>>9.
// ===========================================================================
#define L_STAGE 18432   // halves per stage: As 128x72 + Bs 128x72
#define L_SMEM (2 * L_STAGE * 2)   // 73728 B

__global__ __launch_bounds__(128, 3)
void linh(const __half* __restrict__ A, const __half* __restrict__ W,
          const float* __restrict__ bias_rep, int ldb, int gx, int NT,
          __half* __restrict__ Kh, __half* __restrict__ Vh, __half* __restrict__ Qh,
          float* __restrict__ outf)
{
    extern __shared__ __half sh[];
    const int tid = threadIdx.x;
    const int wid = tid >> 5;
    const int wm = wid >> 1;          // 0..1 (64 rows)
    const int wn = wid & 1;           // 0..1 (64 cols)

    auto issue = [&](int m0, int n0, int k0, int buf) {
        __half* As = sh + buf * L_STAGE;
        __half* Bs = As + 128 * 72;
#pragma unroll
        for (int i = 0; i < 8; i++) {
            const int f = tid + i * 128;
            const int row = f >> 3, c8 = f & 7;
            CP16(As + row * 72 + c8 * 8, A + (size_t)(m0 + row) * DD + k0 + c8 * 8);
        }
#pragma unroll
        for (int i = 0; i < 8; i++) {
            const int f = tid + i * 128;
            const int row = f >> 3, c8 = f & 7;
            CP16(Bs + row * 72 + c8 * 8, W + (size_t)(n0 + row) * DD + k0 + c8 * 8);
        }
        CP_COMMIT();
    };

    const int NC = DD / 64;   // 8
    int tile = blockIdx.x;
    int buf = 0;
    {
        const int n0 = (tile % gx) * 128, m0 = (tile / gx) * 128;
        issue(m0, n0, 0, buf);
    }

    for (; tile < NT; tile += NPERS) {
        const int n0 = (tile % gx) * 128, m0 = (tile / gx) * 128;

        wmma::fragment<wmma::accumulator, 16, 16, 16, float> c[4][4];
#pragma unroll
        for (int i = 0; i < 4; i++)
#pragma unroll
            for (int j = 0; j < 4; j++)
                wmma::load_matrix_sync(c[i][j],
                    bias_rep + n0 + wn * 64 + j * 16, ldb, wmma::mem_row_major);

        for (int ch = 0; ch < NC; ch++) {
            CP_WAIT0();
            __syncthreads();
            const int ib = buf ^ 1;
            if (ch + 1 < NC) {
                issue(m0, n0, (ch + 1) * 64, ib);
            } else {
                const int nt = tile + NPERS;
                if (nt < NT)
                    issue((nt / gx) * 128, (nt % gx) * 128, 0, ib);
            }

            const __half* As = sh + buf * L_STAGE;
            const __half* Bs = As + 128 * 72;
#pragma unroll
            for (int kk = 0; kk < 4; kk++) {
                wmma::fragment<wmma::matrix_a, 16, 16, 16, __half, wmma::row_major> a[4];
                wmma::fragment<wmma::matrix_b, 16, 16, 16, __half, wmma::col_major> b[4];
#pragma unroll
                for (int i = 0; i < 4; i++)
                    wmma::load_matrix_sync(a[i], As + (wm * 64 + i * 16) * 72 + kk * 16, 72);
#pragma unroll
                for (int j = 0; j < 4; j++)
                    wmma::load_matrix_sync(b[j], Bs + (wn * 64 + j * 16) * 72 + kk * 16, 72);
#pragma unroll
                for (int i = 0; i < 4; i++)
#pragma unroll
                    for (int j = 0; j < 4; j++)
                        wmma::mma_sync(c[i][j], a[i], b[j], c[i][j]);
            }
            buf ^= 1;
        }

        // Epilogue (fragment-only, no smem) — overlaps the already-issued
        // prefetch of the next tile's first chunk.
        if (outf) {
#pragma unroll
            for (int i = 0; i < 4; i++)
#pragma unroll
                for (int j = 0; j < 4; j++)
                    wmma::store_matrix_sync(outf + (size_t)(m0 + wm * 64 + i * 16) * DD
                                                 + n0 + wn * 64 + j * 16,
                                            c[i][j], DD, wmma::mem_row_major);
        } else {
            const int mat = n0 >> 9;
            __half* dst = (mat == 0) ? Kh : (mat == 1) ? Vh : Qh;
            const int col0 = n0 & 511;
            wmma::fragment<wmma::accumulator, 16, 16, 16, __half> chf;
#pragma unroll
            for (int i = 0; i < 4; i++)
#pragma unroll
                for (int j = 0; j < 4; j++) {
#pragma unroll
                    for (int e = 0; e < chf.num_elements; e++)
                        chf.x[e] = __float2half(c[i][j].x[e]);
                    wmma::store_matrix_sync(dst + (size_t)(m0 + wm * 64 + i * 16) * DD
                                                + col0 + wn * 64 + j * 16,
                                            chf, DD, wmma::mem_row_major);
                }
        }
    }
}

// ===========================================================================
// Persistent attention (fp16 WMMA): num = expw @ EKV, den = expw @ EK.
// K(s)-chunk 64, double buffer, cross-tile prefetch. Fragment epilogue:
// Yt = half( sigmoid(Qh) * cN/cD )  (bq pre-folded into Qh).
// Tile = 128(t) x 64(d) x batch; decode: d = tile&7, t = (tile>>3)&7, b = tile>>6.
// ===========================================================================
#define A_STAGE 18432   // halves per stage: Ws 128x72 + EK 64x72 + EKV 64x72
#define A_SMEM (2 * A_STAGE * 2)   // 73728 B
#define A_NT 2048

__global__ __launch_bounds__(128, 3)
void attnh(const __half* __restrict__ expw, const __half* __restrict__ EK,
           const __half* __restrict__ EKV, const __half* __restrict__ Qh,
           __half* __restrict__ Yt)
{
    extern __shared__ __half sh[];
    const int tid = threadIdx.x;
    const int wid = tid >> 5;
    const int wm = wid >> 1;          // 0..1 (64 t-rows)
    const int wn = wid & 1;           // 0..1 (32 d-cols)

    auto issue = [&](int t0, int d0, int b, int s0, int buf) {
        __half* Ws  = sh + buf * A_STAGE;
        __half* EKs = Ws + 128 * 72;
        __half* EVs = EKs + 64 * 72;
        const __half* ekp = EK  + (size_t)b * TT * DD + d0;
        const __half* evp = EKV + (size_t)b * TT * DD + d0;
#pragma unroll
        for (int i = 0; i < 8; i++) {          // Ws: 128x64 -> 1024 cp16
            const int f = tid + i * 128;
            const int row = f >> 3, c8 = f & 7;
            CP16(Ws + row * 72 + c8 * 8, expw + (size_t)(t0 + row) * TT + s0 + c8 * 8);
        }
#pragma unroll
        for (int i = 0; i < 4; i++) {          // EK/EKV: 64x64 -> 512 cp16 each
            const int f = tid + i * 128;
            const int row = f >> 3, c8 = f & 7;
            CP16(EKs + row * 72 + c8 * 8, ekp + (size_t)(s0 + row) * DD + c8 * 8);
            CP16(EVs + row * 72 + c8 * 8, evp + (size_t)(s0 + row) * DD + c8 * 8);
        }
        CP_COMMIT();
    };

    const int NC = TT / 64;   // 16
    int tile = blockIdx.x;
    int buf = 0;
    issue(((tile >> 3) & 7) * 128, (tile & 7) * 64, tile >> 6, 0, buf);

    for (; tile < A_NT; tile += NPERS) {
        const int d0 = (tile & 7) * 64;
        const int t0 = ((tile >> 3) & 7) * 128;
        const int b  = tile >> 6;

        wmma::fragment<wmma::accumulator, 16, 16, 16, float> cN[4][2], cD[4][2];
#pragma unroll
        for (int i = 0; i < 4; i++)
#pragma unroll
            for (int j = 0; j < 2; j++) {
                wmma::fill_fragment(cN[i][j], 0.0f);
                wmma::fill_fragment(cD[i][j], 0.0f);
            }

        for (int ch = 0; ch < NC; ch++) {
            CP_WAIT0();
            __syncthreads();
            const int ib = buf ^ 1;
            if (ch + 1 < NC) {
                issue(t0, d0, b, (ch + 1) * 64, ib);
            } else {
                const int nt = tile + NPERS;
                if (nt < A_NT)
                    issue(((nt >> 3) & 7) * 128, (nt & 7) * 64, nt >> 6, 0, ib);
            }

            const __half* Ws  = sh + buf * A_STAGE;
            const __half* EKs = Ws + 128 * 72;
            const __half* EVs = EKs + 64 * 72;
#pragma unroll
            for (int kk = 0; kk < 4; kk++) {
                wmma::fragment<wmma::matrix_a, 16, 16, 16, __half, wmma::row_major> a[4];
                wmma::fragment<wmma::matrix_b, 16, 16, 16, __half, wmma::row_major> bK[2], bV[2];
#pragma unroll
                for (int i = 0; i < 4; i++)
                    wmma::load_matrix_sync(a[i], Ws + (wm * 64 + i * 16) * 72 + kk * 16, 72);
#pragma unroll
                for (int j = 0; j < 2; j++) {
                    wmma::load_matrix_sync(bK[j], EKs + (kk * 16) * 72 + wn * 32 + j * 16, 72);
                    wmma::load_matrix_sync(bV[j], EVs + (kk * 16) * 72 + wn * 32 + j * 16, 72);
                }
#pragma unroll
                for (int i = 0; i < 4; i++)
#pragma unroll
                    for (int j = 0; j < 2; j++) {
                        wmma::mma_sync(cN[i][j], a[i], bV[j], cN[i][j]);
                        wmma::mma_sync(cD[i][j], a[i], bK[j], cD[i][j]);
                    }
            }
            buf ^= 1;
        }

        // Fragment-only epilogue (no smem) — overlaps next-tile prefetch.
        wmma::fragment<wmma::accumulator, 16, 16, 16, __half> qf, yf;
#pragma unroll
        for (int i = 0; i < 4; i++)
#pragma unroll
            for (int j = 0; j < 2; j++) {
                const size_t tp = ((size_t)b * TT + t0 + wm * 64 + i * 16) * DD
                                + d0 + wn * 32 + j * 16;
                wmma::load_matrix_sync(qf, Qh + tp, DD, wmma::mem_row_major);
#pragma unroll
                for (int e = 0; e < qf.num_elements; e++) {
                    const float q = __half2float(qf.x[e]);
                    const float r = cN[i][j].x[e] / cD[i][j].x[e];
                    yf.x[e] = __float2half((1.f / (1.f + expf(-q))) * r);
                }
                wmma::store_matrix_sync(Yt + tp, yf, DD, wmma::mem_row_major);
            }
    }
}

// ===========================================================================
// Fused batch-max + exp + bias-fold over half K/V (4 halves / thread)
// ===========================================================================
__global__ __launch_bounds__(128)
void kmax_ekv_kernel(const __half* __restrict__ Kh, const __half* __restrict__ Vh,
                     const float* __restrict__ bv,
                     __half* __restrict__ EK, __half* __restrict__ EKV)
{
    const int idx = (blockIdx.x * 128 + threadIdx.x) * 4;   // < TT*DD
    const float4 bvv = __ldg((const float4*)(bv + (idx & (DD - 1))));

    uint2 kvh[BB];
    __half2 m0 = __float2half2_rn(-65504.f), m1 = m0;
#pragma unroll
    for (int b = 0; b < BB; b++) {
        kvh[b] = *(const uint2*)(Kh + (size_t)b * TT * DD + idx);
        m0 = __hmax2(m0, *(const __half2*)&kvh[b].x);
        m1 = __hmax2(m1, *(const __half2*)&kvh[b].y);
    }
    const float2 mf0 = __half22float2(m0);
    const float2 mf1 = __half22float2(m1);
#pragma unroll
    for (int b = 0; b < BB; b++) {
        const size_t gi = (size_t)b * TT * DD + idx;
        uint2 vv = *(const uint2*)(Vh + gi);
        float2 k0 = __half22float2(*(const __half2*)&kvh[b].x);
        float2 k1 = __half22float2(*(const __half2*)&kvh[b].y);
        float2 v0 = __half22float2(*(const __half2*)&vv.x);
        float2 v1 = __half22float2(*(const __half2*)&vv.y);
        const float e0 = expf(k0.x - mf0.x);
        const float e1 = expf(k0.y - mf0.y);
        const float e2 = expf(k1.x - mf1.x);
        const float e3 = expf(k1.y - mf1.y);
        uint2 ek, ekv;
        *(__half2*)&ek.x  = __floats2half2_rn(e0, e1);
        *(__half2*)&ek.y  = __floats2half2_rn(e2, e3);
        *(__half2*)&ekv.x = __floats2half2_rn(e0 * (v0.x + bvv.x), e1 * (v0.y + bvv.y));
        *(__half2*)&ekv.y = __floats2half2_rn(e2 * (v1.x + bvv.z), e3 * (v1.y + bvv.w));
        *(uint2*)(EK + gi)  = ek;
        *(uint2*)(EKV + gi) = ekv;
    }
}

// ===========================================================================
// Merged prep: f2h(x) [blocks 0..16383], wconv [16384..17407],
// brep+brep3 [17408..17535], expw rows [17536..18559]
// ===========================================================================
__global__ __launch_bounds__(256)
void prep_kernel(const float* __restrict__ x, __half* __restrict__ xh,
                 const float* __restrict__ Wk, const float* __restrict__ Wv,
                 const float* __restrict__ Wq, const float* __restrict__ Wo,
                 __half* __restrict__ W3h, __half* __restrict__ Woh,
                 const float* __restrict__ bo, float* __restrict__ brep,
                 const float* __restrict__ bq, float* __restrict__ brep3,
                 const float* __restrict__ w, __half* __restrict__ ew)
{
    const int blk = blockIdx.x;
    if (blk < 16384) {
        const size_t f = (size_t)blk * 256 + threadIdx.x;   // f4 index over x
        float4 v = ((const float4*)x)[f];
        __half2* d = (__half2*)(xh + f * 4);
        d[0] = __floats2half2_rn(v.x, v.y);
        d[1] = __floats2half2_rn(v.z, v.w);
    } else if (blk < 17408) {
        const int f = (blk - 16384) * 256 + threadIdx.x;    // f4 index < 4*65536
        const int per = DD * DD / 4;
        const float* src; __half* dst; int off;
        if (f < per)           { src = Wk; dst = W3h;            off = f; }
        else if (f < 2 * per)  { src = Wv; dst = W3h + DD * DD;  off = f - per; }
        else if (f < 3 * per)  { src = Wq; dst = W3h + 2*DD*DD;  off = f - 2 * per; }
        else                   { src = Wo; dst = Woh;            off = f - 3 * per; }
        float4 v = ((const float4*)src)[off];
        __half2* d = (__half2*)(dst + (size_t)off * 4);
        d[0] = __floats2half2_rn(v.x, v.y);
        d[1] = __floats2half2_rn(v.z, v.w);
    } else if (blk < 17440) {
        const int idx = (blk - 17408) * 256 + threadIdx.x;  // < 16*DD
        brep[idx] = bo[idx & (DD - 1)];
    } else if (blk < 17536) {
        const int idx = (blk - 17440) * 256 + threadIdx.x;  // < 16*1536
        const int col = idx % (3 * DD);
        brep3[idx] = (col >= 2 * DD) ? bq[col - 2 * DD] : 0.0f;
    } else {
        const int t = blk - 17536;
        const float* row = w + (size_t)t * TT;
        float m = -INFINITY;
        for (int i = threadIdx.x; i < TT; i += 256) m = fmaxf(m, row[i]);
#pragma unroll
        for (int o = 16; o > 0; o >>= 1)
            m = fmaxf(m, __shfl_xor_sync(0xffffffffu, m, o));
        __shared__ float warpmax[8];
        __shared__ float rowmax;
        if ((threadIdx.x & 31) == 0) warpmax[threadIdx.x >> 5] = m;
        __syncthreads();
        if (threadIdx.x == 0) {
            float mm = warpmax[0];
#pragma unroll
            for (int i = 1; i < 8; i++) mm = fmaxf(mm, warpmax[i]);
            rowmax = mm;
        }
        __syncthreads();
        const float rm = rowmax;
        for (int i = threadIdx.x; i < TT; i += 256)
            ew[(size_t)t * TT + i] = __float2half(expf(row[i] - rm));
    }
}

// ===========================================================================
extern "C" void kernel_launch(void* const* d_in, const int* in_sizes, int n_in,
                              void* d_out, int out_size)
{
    const float* x    = (const float*)d_in[0];
    const float* Wk_w = (const float*)d_in[1];
    // Wk_b unused: K bias cancels inside exp(K - max_b K)
    const float* Wv_w = (const float*)d_in[3];
    const float* Wv_b = (const float*)d_in[4];
    const float* Wq_w = (const float*)d_in[5];
    const float* Wq_b = (const float*)d_in[6];
    const float* w    = (const float*)d_in[7];
    const float* Wo_w = (const float*)d_in[8];
    const float* Wo_b = (const float*)d_in[9];
    float* out = (float*)d_out;

    float *pbrep, *pbrep3;
    __half *pKh, *pVh, *pQh, *pxh, *pW3h, *pWoh, *pexpwh, *pEKh, *pEKVh, *pYth;
    cudaGetSymbolAddress((void**)&pbrep, g_brep);
    cudaGetSymbolAddress((void**)&pbrep3, g_brep3);
    cudaGetSymbolAddress((void**)&pKh, g_Kh);
    cudaGetSymbolAddress((void**)&pVh, g_Vh);
    cudaGetSymbolAddress((void**)&pQh, g_Qh);
    cudaGetSymbolAddress((void**)&pxh, g_xh);
    cudaGetSymbolAddress((void**)&pW3h, g_W3h);
    cudaGetSymbolAddress((void**)&pWoh, g_Woh);
    cudaGetSymbolAddress((void**)&pexpwh, g_expwh);
    cudaGetSymbolAddress((void**)&pEKh, g_EKh);
    cudaGetSymbolAddress((void**)&pEKVh, g_EKVh);
    cudaGetSymbolAddress((void**)&pYth, g_Yth);

    cudaFuncSetAttribute(linh,  cudaFuncAttributeMaxDynamicSharedMemorySize, L_SMEM);
    cudaFuncSetAttribute(attnh, cudaFuncAttributeMaxDynamicSharedMemorySize, A_SMEM);

    // #1 prep (f2h + wconv + brep/brep3 + expw)
    prep_kernel<<<18560, 256>>>(x, pxh, Wk_w, Wv_w, Wq_w, Wo_w, pW3h, pWoh,
                                Wo_b, pbrep, Wq_b, pbrep3, w, pexpwh);

    // #2 fused K/V/Q linear (half out, bq folded into Q): 3072 tiles, gx=12
    linh<<<NPERS, 128, L_SMEM>>>(pxh, pW3h, pbrep3, 3 * DD, 12, 3072,
                                 pKh, pVh, pQh, nullptr);

    // #3 fused batch-max + exp (+ V bias)
    kmax_ekv_kernel<<<(TT * DD / 4) / 128, 128>>>(pKh, pVh, Wv_b, pEKh, pEKVh);

    // #4 attention (persistent, fragment epilogue)
    attnh<<<NPERS, 128, A_SMEM>>>(pexpwh, pEKh, pEKVh, pQh, pYth);

    // #5 final linear with Wo bias (fp32 out): 1024 tiles, gx=4
    linh<<<NPERS, 128, L_SMEM>>>(pYth, pWoh, pbrep, DD, 4, 1024,
                                 nullptr, nullptr, nullptr, out);
}

// round 16
// speedup vs baseline: 1.0222x; 1.0222x over previous
#include <cuda_runtime.h>
#include <cuda_fp16.h>
#include <math.h>
#include <mma.h>
#include <stdint.h>

using namespace nvcuda;

#define BB 32
#define TT 1024
#define DD 512
#define MM (BB * TT)
#define NPERS 444   // 148 SMs x 3 CTAs

// Scratch (__device__ globals; no allocations allowed)
__device__ float  g_brep[16 * DD];        // replicated Wo bias (final linear)
__device__ float  g_brep3[16 * 3 * DD];   // replicated [0 | 0 | bq] (fused linear)
__device__ int    g_ctr[4];               // work-stealing counters
__device__ __half g_Kh[MM * DD];
__device__ __half g_Vh[MM * DD];
__device__ __half g_Qh[MM * DD];
__device__ __half g_xh[MM * DD];
__device__ __half g_W3h[3 * DD * DD];
__device__ __half g_Woh[DD * DD];
__device__ __half g_expwh[TT * TT];
__device__ __half g_EKh[MM * DD];
__device__ __half g_EKVh[MM * DD];
__device__ __half g_Yth[MM * DD];

__device__ __forceinline__ uint32_t smem_u32(const void* p) {
    uint32_t a;
    asm("{ .reg .u64 t; cvta.to.shared.u64 t, %1; cvt.u32.u64 %0, t; }"
        : "=r"(a) : "l"(p));
    return a;
}

#define CP16(dst, src) \
    asm volatile("cp.async.cg.shared.global [%0], [%1], 16;" \
        :: "r"(smem_u32(dst)), "l"((const void*)(src)) : "memory")
#define CP_COMMIT() asm volatile("cp.async.commit_group;" ::: "memory")
#define CP_WAIT0()  asm volatile("cp.async.wait_group 0;" ::: "memory")

// ===========================================================================
// Persistent linear NT GEMM with atomic work-stealing (fp16 WMMA, fp32 acc,
// K-chunk 64, double buffer, cross-tile prefetch).
// Block tile 128x128, 128 threads, warp tile 64x64. grid = NPERS.
// Fused mode (outf==null): convert acc to half, route to Kh/Vh/Qh by n>>9.
// ===========================================================================
#define L_STAGE 18432   // halves per stage: As 128x72 + Bs 128x72
#define L_SMEM (2 * L_STAGE * 2)   // 73728 B

__global__ __launch_bounds__(128, 3)
void linh(const __half* __restrict__ A, const __half* __restrict__ W,
          const float* __restrict__ bias_rep, int ldb, int gx, int NT, int* ctr,
          __half* __restrict__ Kh, __half* __restrict__ Vh, __half* __restrict__ Qh,
          float* __restrict__ outf)
{
    extern __shared__ __half sh[];
    __shared__ int s_next;
    const int tid = threadIdx.x;
    const int wid = tid >> 5;
    const int wm = wid >> 1;          // 0..1 (64 rows)
    const int wn = wid & 1;           // 0..1 (64 cols)

    auto issue = [&](int m0, int n0, int k0, int buf) {
        __half* As = sh + buf * L_STAGE;
        __half* Bs = As + 128 * 72;
#pragma unroll
        for (int i = 0; i < 8; i++) {
            const int f = tid + i * 128;
            const int row = f >> 3, c8 = f & 7;
            CP16(As + row * 72 + c8 * 8, A + (size_t)(m0 + row) * DD + k0 + c8 * 8);
        }
#pragma unroll
        for (int i = 0; i < 8; i++) {
            const int f = tid + i * 128;
            const int row = f >> 3, c8 = f & 7;
            CP16(Bs + row * 72 + c8 * 8, W + (size_t)(n0 + row) * DD + k0 + c8 * 8);
        }
        CP_COMMIT();
    };

    const int NC = DD / 64;   // 8
    if (tid == 0) s_next = atomicAdd(ctr, 1);
    __syncthreads();
    int tile = s_next;
    int buf = 0;
    if (tile < NT)
        issue((tile / gx) * 128, (tile % gx) * 128, 0, buf);

    while (tile < NT) {
        const int n0 = (tile % gx) * 128, m0 = (tile / gx) * 128;

        wmma::fragment<wmma::accumulator, 16, 16, 16, float> c[4][4];
#pragma unroll
        for (int i = 0; i < 4; i++)
#pragma unroll
            for (int j = 0; j < 4; j++)
                wmma::load_matrix_sync(c[i][j],
                    bias_rep + n0 + wn * 64 + j * 16, ldb, wmma::mem_row_major);

        for (int ch = 0; ch < NC; ch++) {
            CP_WAIT0();
            __syncthreads();   // also publishes s_next written at ch == NC-2
            const int ib = buf ^ 1;
            if (ch + 1 < NC) {
                issue(m0, n0, (ch + 1) * 64, ib);
            } else {
                const int nt = s_next;
                if (nt < NT)
                    issue((nt / gx) * 128, (nt % gx) * 128, 0, ib);
            }
            if (ch == NC - 2 && tid == 0) s_next = atomicAdd(ctr, 1);

            const __half* As = sh + buf * L_STAGE;
            const __half* Bs = As + 128 * 72;
#pragma unroll
            for (int kk = 0; kk < 4; kk++) {
                wmma::fragment<wmma::matrix_a, 16, 16, 16, __half, wmma::row_major> a[4];
                wmma::fragment<wmma::matrix_b, 16, 16, 16, __half, wmma::col_major> b[4];
#pragma unroll
                for (int i = 0; i < 4; i++)
                    wmma::load_matrix_sync(a[i], As + (wm * 64 + i * 16) * 72 + kk * 16, 72);
#pragma unroll
                for (int j = 0; j < 4; j++)
                    wmma::load_matrix_sync(b[j], Bs + (wn * 64 + j * 16) * 72 + kk * 16, 72);
#pragma unroll
                for (int i = 0; i < 4; i++)
#pragma unroll
                    for (int j = 0; j < 4; j++)
                        wmma::mma_sync(c[i][j], a[i], b[j], c[i][j]);
            }
            buf ^= 1;
        }

        // Fragment-only epilogue — overlaps the already-issued next-tile prefetch.
        if (outf) {
#pragma unroll
            for (int i = 0; i < 4; i++)
#pragma unroll
                for (int j = 0; j < 4; j++)
                    wmma::store_matrix_sync(outf + (size_t)(m0 + wm * 64 + i * 16) * DD
                                                 + n0 + wn * 64 + j * 16,
                                            c[i][j], DD, wmma::mem_row_major);
        } else {
            const int mat = n0 >> 9;
            __half* dst = (mat == 0) ? Kh : (mat == 1) ? Vh : Qh;
            const int col0 = n0 & 511;
            wmma::fragment<wmma::accumulator, 16, 16, 16, __half> chf;
#pragma unroll
            for (int i = 0; i < 4; i++)
#pragma unroll
                for (int j = 0; j < 4; j++) {
#pragma unroll
                    for (int e = 0; e < chf.num_elements; e++)
                        chf.x[e] = __float2half(c[i][j].x[e]);
                    wmma::store_matrix_sync(dst + (size_t)(m0 + wm * 64 + i * 16) * DD
                                                + col0 + wn * 64 + j * 16,
                                            chf, DD, wmma::mem_row_major);
                }
        }
        tile = s_next;   // published by the ch == NC-1 __syncthreads
    }
}

// ===========================================================================
// Persistent attention with atomic work-stealing (fp16 WMMA).
// num = expw @ EKV, den = expw @ EK; Yt = half(sigmoid(Qh) * cN/cD)
// (bq pre-folded into Qh). Tile = 128(t) x 64(d) x batch;
// decode: d = tile&7, t = (tile>>3)&7, b = tile>>6.  A_NT = 2048.
// ===========================================================================
#define A_STAGE 18432   // halves per stage: Ws 128x72 + EK 64x72 + EKV 64x72
#define A_SMEM (2 * A_STAGE * 2)   // 73728 B
#define A_NT 2048

__global__ __launch_bounds__(128, 3)
void attnh(const __half* __restrict__ expw, const __half* __restrict__ EK,
           const __half* __restrict__ EKV, const __half* __restrict__ Qh,
           int* ctr, __half* __restrict__ Yt)
{
    extern __shared__ __half sh[];
    __shared__ int s_next;
    const int tid = threadIdx.x;
    const int wid = tid >> 5;
    const int wm = wid >> 1;          // 0..1 (64 t-rows)
    const int wn = wid & 1;           // 0..1 (32 d-cols)

    auto issue = [&](int t0, int d0, int b, int s0, int buf) {
        __half* Ws  = sh + buf * A_STAGE;
        __half* EKs = Ws + 128 * 72;
        __half* EVs = EKs + 64 * 72;
        const __half* ekp = EK  + (size_t)b * TT * DD + d0;
        const __half* evp = EKV + (size_t)b * TT * DD + d0;
#pragma unroll
        for (int i = 0; i < 8; i++) {          // Ws: 128x64 -> 1024 cp16
            const int f = tid + i * 128;
            const int row = f >> 3, c8 = f & 7;
            CP16(Ws + row * 72 + c8 * 8, expw + (size_t)(t0 + row) * TT + s0 + c8 * 8);
        }
#pragma unroll
        for (int i = 0; i < 4; i++) {          // EK/EKV: 64x64 -> 512 cp16 each
            const int f = tid + i * 128;
            const int row = f >> 3, c8 = f & 7;
            CP16(EKs + row * 72 + c8 * 8, ekp + (size_t)(s0 + row) * DD + c8 * 8);
            CP16(EVs + row * 72 + c8 * 8, evp + (size_t)(s0 + row) * DD + c8 * 8);
        }
        CP_COMMIT();
    };

    const int NC = TT / 64;   // 16
    if (tid == 0) s_next = atomicAdd(ctr, 1);
    __syncthreads();
    int tile = s_next;
    int buf = 0;
    if (tile < A_NT)
        issue(((tile >> 3) & 7) * 128, (tile & 7) * 64, tile >> 6, 0, buf);

    while (tile < A_NT) {
        const int d0 = (tile & 7) * 64;
        const int t0 = ((tile >> 3) & 7) * 128;
        const int b  = tile >> 6;

        wmma::fragment<wmma::accumulator, 16, 16, 16, float> cN[4][2], cD[4][2];
#pragma unroll
        for (int i = 0; i < 4; i++)
#pragma unroll
            for (int j = 0; j < 2; j++) {
                wmma::fill_fragment(cN[i][j], 0.0f);
                wmma::fill_fragment(cD[i][j], 0.0f);
            }

        for (int ch = 0; ch < NC; ch++) {
            CP_WAIT0();
            __syncthreads();   // also publishes s_next written at ch == NC-2
            const int ib = buf ^ 1;
            if (ch + 1 < NC) {
                issue(t0, d0, b, (ch + 1) * 64, ib);
            } else {
                const int nt = s_next;
                if (nt < A_NT)
                    issue(((nt >> 3) & 7) * 128, (nt & 7) * 64, nt >> 6, 0, ib);
            }
            if (ch == NC - 2 && tid == 0) s_next = atomicAdd(ctr, 1);

            const __half* Ws  = sh + buf * A_STAGE;
            const __half* EKs = Ws + 128 * 72;
            const __half* EVs = EKs + 64 * 72;
#pragma unroll
            for (int kk = 0; kk < 4; kk++) {
                wmma::fragment<wmma::matrix_a, 16, 16, 16, __half, wmma::row_major> a[4];
                wmma::fragment<wmma::matrix_b, 16, 16, 16, __half, wmma::row_major> bK[2], bV[2];
#pragma unroll
                for (int i = 0; i < 4; i++)
                    wmma::load_matrix_sync(a[i], Ws + (wm * 64 + i * 16) * 72 + kk * 16, 72);
#pragma unroll
                for (int j = 0; j < 2; j++) {
                    wmma::load_matrix_sync(bK[j], EKs + (kk * 16) * 72 + wn * 32 + j * 16, 72);
                    wmma::load_matrix_sync(bV[j], EVs + (kk * 16) * 72 + wn * 32 + j * 16, 72);
                }
#pragma unroll
                for (int i = 0; i < 4; i++)
#pragma unroll
                    for (int j = 0; j < 2; j++) {
                        wmma::mma_sync(cN[i][j], a[i], bV[j], cN[i][j]);
                        wmma::mma_sync(cD[i][j], a[i], bK[j], cD[i][j]);
                    }
            }
            buf ^= 1;
        }

        // Fragment-only epilogue — overlaps next-tile prefetch.
        wmma::fragment<wmma::accumulator, 16, 16, 16, __half> qf, yf;
#pragma unroll
        for (int i = 0; i < 4; i++)
#pragma unroll
            for (int j = 0; j < 2; j++) {
                const size_t tp = ((size_t)b * TT + t0 + wm * 64 + i * 16) * DD
                                + d0 + wn * 32 + j * 16;
                wmma::load_matrix_sync(qf, Qh + tp, DD, wmma::mem_row_major);
#pragma unroll
                for (int e = 0; e < qf.num_elements; e++) {
                    const float q = __half2float(qf.x[e]);
                    const float r = cN[i][j].x[e] / cD[i][j].x[e];
                    yf.x[e] = __float2half((1.f / (1.f + expf(-q))) * r);
                }
                wmma::store_matrix_sync(Yt + tp, yf, DD, wmma::mem_row_major);
            }
        tile = s_next;
    }
}

// ===========================================================================
// Fused batch-max + exp + bias-fold over half K/V (4 halves / thread)
// ===========================================================================
__global__ __launch_bounds__(128)
void kmax_ekv_kernel(const __half* __restrict__ Kh, const __half* __restrict__ Vh,
                     const float* __restrict__ bv,
                     __half* __restrict__ EK, __half* __restrict__ EKV)
{
    const int idx = (blockIdx.x * 128 + threadIdx.x) * 4;   // < TT*DD
    const float4 bvv = __ldg((const float4*)(bv + (idx & (DD - 1))));

    uint2 kvh[BB];
    __half2 m0 = __float2half2_rn(-65504.f), m1 = m0;
#pragma unroll
    for (int b = 0; b < BB; b++) {
        kvh[b] = *(const uint2*)(Kh + (size_t)b * TT * DD + idx);
        m0 = __hmax2(m0, *(const __half2*)&kvh[b].x);
        m1 = __hmax2(m1, *(const __half2*)&kvh[b].y);
    }
    const float2 mf0 = __half22float2(m0);
    const float2 mf1 = __half22float2(m1);
#pragma unroll
    for (int b = 0; b < BB; b++) {
        const size_t gi = (size_t)b * TT * DD + idx;
        uint2 vv = *(const uint2*)(Vh + gi);
        float2 k0 = __half22float2(*(const __half2*)&kvh[b].x);
        float2 k1 = __half22float2(*(const __half2*)&kvh[b].y);
        float2 v0 = __half22float2(*(const __half2*)&vv.x);
        float2 v1 = __half22float2(*(const __half2*)&vv.y);
        const float e0 = expf(k0.x - mf0.x);
        const float e1 = expf(k0.y - mf0.y);
        const float e2 = expf(k1.x - mf1.x);
        const float e3 = expf(k1.y - mf1.y);
        uint2 ek, ekv;
        *(__half2*)&ek.x  = __floats2half2_rn(e0, e1);
        *(__half2*)&ek.y  = __floats2half2_rn(e2, e3);
        *(__half2*)&ekv.x = __floats2half2_rn(e0 * (v0.x + bvv.x), e1 * (v0.y + bvv.y));
        *(__half2*)&ekv.y = __floats2half2_rn(e2 * (v1.x + bvv.z), e3 * (v1.y + bvv.w));
        *(uint2*)(EK + gi)  = ek;
        *(uint2*)(EKV + gi) = ekv;
    }
}

// ===========================================================================
// Merged prep: f2h(x) [blocks 0..16383], wconv [16384..17407],
// brep + counter reset [17408..17439], brep3 [17440..17535],
// expw rows [17536..18559]
// ===========================================================================
__global__ __launch_bounds__(256)
void prep_kernel(const float* __restrict__ x, __half* __restrict__ xh,
                 const float* __restrict__ Wk, const float* __restrict__ Wv,
                 const float* __restrict__ Wq, const float* __restrict__ Wo,
                 __half* __restrict__ W3h, __half* __restrict__ Woh,
                 const float* __restrict__ bo, float* __restrict__ brep,
                 const float* __restrict__ bq, float* __restrict__ brep3,
                 const float* __restrict__ w, __half* __restrict__ ew)
{
    const int blk = blockIdx.x;
    if (blk < 16384) {
        const size_t f = (size_t)blk * 256 + threadIdx.x;   // f4 index over x
        float4 v = ((const float4*)x)[f];
        __half2* d = (__half2*)(xh + f * 4);
        d[0] = __floats2half2_rn(v.x, v.y);
        d[1] = __floats2half2_rn(v.z, v.w);
    } else if (blk < 17408) {
        const int f = (blk - 16384) * 256 + threadIdx.x;    // f4 index < 4*65536
        const int per = DD * DD / 4;
        const float* src; __half* dst; int off;
        if (f < per)           { src = Wk; dst = W3h;            off = f; }
        else if (f < 2 * per)  { src = Wv; dst = W3h + DD * DD;  off = f - per; }
        else if (f < 3 * per)  { src = Wq; dst = W3h + 2*DD*DD;  off = f - 2 * per; }
        else                   { src = Wo; dst = Woh;            off = f - 3 * per; }
        float4 v = ((const float4*)src)[off];
        __half2* d = (__half2*)(dst + (size_t)off * 4);
        d[0] = __floats2half2_rn(v.x, v.y);
        d[1] = __floats2half2_rn(v.z, v.w);
    } else if (blk < 17440) {
        const int idx = (blk - 17408) * 256 + threadIdx.x;  // < 16*DD
        brep[idx] = bo[idx & (DD - 1)];
        if (blk == 17408 && threadIdx.x < 4) g_ctr[threadIdx.x] = 0;
    } else if (blk < 17536) {
        const int idx = (blk - 17440) * 256 + threadIdx.x;  // < 16*1536
        const int col = idx % (3 * DD);
        brep3[idx] = (col >= 2 * DD) ? bq[col - 2 * DD] : 0.0f;
    } else {
        const int t = blk - 17536;
        const float* row = w + (size_t)t * TT;
        float m = -INFINITY;
        for (int i = threadIdx.x; i < TT; i += 256) m = fmaxf(m, row[i]);
#pragma unroll
        for (int o = 16; o > 0; o >>= 1)
            m = fmaxf(m, __shfl_xor_sync(0xffffffffu, m, o));
        __shared__ float warpmax[8];
        __shared__ float rowmax;
        if ((threadIdx.x & 31) == 0) warpmax[threadIdx.x >> 5] = m;
        __syncthreads();
        if (threadIdx.x == 0) {
            float mm = warpmax[0];
#pragma unroll
            for (int i = 1; i < 8; i++) mm = fmaxf(mm, warpmax[i]);
            rowmax = mm;
        }
        __syncthreads();
        const float rm = rowmax;
        for (int i = threadIdx.x; i < TT; i += 256)
            ew[(size_t)t * TT + i] = __float2half(expf(row[i] - rm));
    }
}

// ===========================================================================
extern "C" void kernel_launch(void* const* d_in, const int* in_sizes, int n_in,
                              void* d_out, int out_size)
{
    const float* x    = (const float*)d_in[0];
    const float* Wk_w = (const float*)d_in[1];
    // Wk_b unused: K bias cancels inside exp(K - max_b K)
    const float* Wv_w = (const float*)d_in[3];
    const float* Wv_b = (const float*)d_in[4];
    const float* Wq_w = (const float*)d_in[5];
    const float* Wq_b = (const float*)d_in[6];
    const float* w    = (const float*)d_in[7];
    const float* Wo_w = (const float*)d_in[8];
    const float* Wo_b = (const float*)d_in[9];
    float* out = (float*)d_out;

    float *pbrep, *pbrep3;
    int *pctr;
    __half *pKh, *pVh, *pQh, *pxh, *pW3h, *pWoh, *pexpwh, *pEKh, *pEKVh, *pYth;
    cudaGetSymbolAddress((void**)&pbrep, g_brep);
    cudaGetSymbolAddress((void**)&pbrep3, g_brep3);
    cudaGetSymbolAddress((void**)&pctr, g_ctr);
    cudaGetSymbolAddress((void**)&pKh, g_Kh);
    cudaGetSymbolAddress((void**)&pVh, g_Vh);
    cudaGetSymbolAddress((void**)&pQh, g_Qh);
    cudaGetSymbolAddress((void**)&pxh, g_xh);
    cudaGetSymbolAddress((void**)&pW3h, g_W3h);
    cudaGetSymbolAddress((void**)&pWoh, g_Woh);
    cudaGetSymbolAddress((void**)&pexpwh, g_expwh);
    cudaGetSymbolAddress((void**)&pEKh, g_EKh);
    cudaGetSymbolAddress((void**)&pEKVh, g_EKVh);
    cudaGetSymbolAddress((void**)&pYth, g_Yth);

    cudaFuncSetAttribute(linh,  cudaFuncAttributeMaxDynamicSharedMemorySize, L_SMEM);
    cudaFuncSetAttribute(attnh, cudaFuncAttributeMaxDynamicSharedMemorySize, A_SMEM);

    // #1 prep (f2h + wconv + brep/brep3 + counter reset + expw)
    prep_kernel<<<18560, 256>>>(x, pxh, Wk_w, Wv_w, Wq_w, Wo_w, pW3h, pWoh,
                                Wo_b, pbrep, Wq_b, pbrep3, w, pexpwh);

    // #2 fused K/V/Q linear (half out, bq folded into Q): 3072 tiles, gx=12
    linh<<<NPERS, 128, L_SMEM>>>(pxh, pW3h, pbrep3, 3 * DD, 12, 3072, pctr + 0,
                                 pKh, pVh, pQh, nullptr);

    // #3 fused batch-max + exp (+ V bias)
    kmax_ekv_kernel<<<(TT * DD / 4) / 128, 128>>>(pKh, pVh, Wv_b, pEKh, pEKVh);

    // #4 attention (persistent + stealing, fragment epilogue)
    attnh<<<NPERS, 128, A_SMEM>>>(pexpwh, pEKh, pEKVh, pQh, pctr + 1, pYth);

    // #5 final linear with Wo bias (fp32 out): 1024 tiles, gx=4
    linh<<<NPERS, 128, L_SMEM>>>(pYth, pWoh, pbrep, DD, 4, 1024, pctr + 2,
                                 nullptr, nullptr, nullptr, out);
}

// round 17
// speedup vs baseline: 1.0304x; 1.0080x over previous
#include <cuda_runtime.h>
#include <cuda_fp16.h>
#include <math.h>
#include <mma.h>
#include <stdint.h>

using namespace nvcuda;

#define BB 32
#define TT 1024
#define DD 512
#define MM (BB * TT)
#define NPERS 444   // 148 SMs x 3 CTAs

// Scratch (__device__ globals; no allocations allowed)
__device__ float  g_brep[16 * DD];        // replicated Wo bias (final linear)
__device__ float  g_brep3[16 * 3 * DD];   // replicated [0 | 0 | bq] (fused linear)
__device__ int    g_ctr[4];               // work-stealing counter (attn)
__device__ __half g_Kh[MM * DD];
__device__ __half g_Vh[MM * DD];
__device__ __half g_Qh[MM * DD];
__device__ __half g_xh[MM * DD];
__device__ __half g_W3h[3 * DD * DD];
__device__ __half g_Woh[DD * DD];
__device__ __half g_expwh[TT * TT];
__device__ __half g_EKh[MM * DD];
__device__ __half g_EKVh[MM * DD];
__device__ __half g_Yth[MM * DD];

__device__ __forceinline__ uint32_t smem_u32(const void* p) {
    uint32_t a;
    asm("{ .reg .u64 t; cvta.to.shared.u64 t, %1; cvt.u32.u64 %0, t; }"
        : "=r"(a) : "l"(p));
    return a;
}

#define CP16(dst, src) \
    asm volatile("cp.async.cg.shared.global [%0], [%1], 16;" \
        :: "r"(smem_u32(dst)), "l"((const void*)(src)) : "memory")
#define CP_COMMIT() asm volatile("cp.async.commit_group;" ::: "memory")
#define CP_WAIT0()  asm volatile("cp.async.wait_group 0;" ::: "memory")

// ===========================================================================
// Linear NT GEMM (fp16 WMMA, fp32 acc, K-chunk 64, 2-stage double buffer)
// NON-persistent (R14 proven config). Block 128x128, 128 threads, 4 warps,
// warp tile 64x64. 3 CTAs/SM. Acc init from replicated-bias tile.
// Fused mode (outf==null): convert acc to half, route to Kh/Vh/Qh by n>>9.
// ===========================================================================
#define L_STAGE 18432   // halves per stage: As 128x72 + Bs 128x72
#define L_SMEM (2 * L_STAGE * 2)   // 73728 B

__global__ __launch_bounds__(128, 3)
void linh(const __half* __restrict__ A, const __half* __restrict__ W,
          const float* __restrict__ bias_rep, int ldb,
          __half* __restrict__ Kh, __half* __restrict__ Vh, __half* __restrict__ Qh,
          float* __restrict__ outf)
{
    extern __shared__ __half sh[];
    const int tid = threadIdx.x;
    const int wid = tid >> 5;
    const int wm = wid >> 1;          // 0..1 (64 rows)
    const int wn = wid & 1;           // 0..1 (64 cols)
    const int m0 = blockIdx.y * 128, n0 = blockIdx.x * 128;

    wmma::fragment<wmma::accumulator, 16, 16, 16, float> c[4][4];
#pragma unroll
    for (int i = 0; i < 4; i++)
#pragma unroll
        for (int j = 0; j < 4; j++)
            wmma::load_matrix_sync(c[i][j],
                bias_rep + n0 + wn * 64 + j * 16, ldb, wmma::mem_row_major);

    auto issue = [&](int chunk) {
        __half* As = sh + (chunk & 1) * L_STAGE;
        __half* Bs = As + 128 * 72;
        const int k0 = chunk * 64;
#pragma unroll
        for (int i = 0; i < 8; i++) {
            const int f = tid + i * 128;
            const int row = f >> 3, c8 = f & 7;
            CP16(As + row * 72 + c8 * 8, A + (size_t)(m0 + row) * DD + k0 + c8 * 8);
        }
#pragma unroll
        for (int i = 0; i < 8; i++) {
            const int f = tid + i * 128;
            const int row = f >> 3, c8 = f & 7;
            CP16(Bs + row * 72 + c8 * 8, W + (size_t)(n0 + row) * DD + k0 + c8 * 8);
        }
        CP_COMMIT();
    };

    issue(0);

    const int NC = DD / 64;   // 8
    for (int ch = 0; ch < NC; ch++) {
        CP_WAIT0();
        __syncthreads();
        if (ch + 1 < NC) issue(ch + 1);   // overlaps with compute(ch)

        const __half* As = sh + (ch & 1) * L_STAGE;
        const __half* Bs = As + 128 * 72;
#pragma unroll
        for (int kk = 0; kk < 4; kk++) {
            wmma::fragment<wmma::matrix_a, 16, 16, 16, __half, wmma::row_major> a[4];
            wmma::fragment<wmma::matrix_b, 16, 16, 16, __half, wmma::col_major> b[4];
#pragma unroll
            for (int i = 0; i < 4; i++)
                wmma::load_matrix_sync(a[i], As + (wm * 64 + i * 16) * 72 + kk * 16, 72);
#pragma unroll
            for (int j = 0; j < 4; j++)
                wmma::load_matrix_sync(b[j], Bs + (wn * 64 + j * 16) * 72 + kk * 16, 72);
#pragma unroll
            for (int i = 0; i < 4; i++)
#pragma unroll
                for (int j = 0; j < 4; j++)
                    wmma::mma_sync(c[i][j], a[i], b[j], c[i][j]);
        }
    }

    if (outf) {
#pragma unroll
        for (int i = 0; i < 4; i++)
#pragma unroll
            for (int j = 0; j < 4; j++)
                wmma::store_matrix_sync(outf + (size_t)(m0 + wm * 64 + i * 16) * DD
                                             + n0 + wn * 64 + j * 16,
                                        c[i][j], DD, wmma::mem_row_major);
    } else {
        const int mat = n0 >> 9;
        __half* dst = (mat == 0) ? Kh : (mat == 1) ? Vh : Qh;
        const int col0 = n0 & 511;
        wmma::fragment<wmma::accumulator, 16, 16, 16, __half> chf;
#pragma unroll
        for (int i = 0; i < 4; i++)
#pragma unroll
            for (int j = 0; j < 4; j++) {
#pragma unroll
                for (int e = 0; e < chf.num_elements; e++)
                    chf.x[e] = __float2half(c[i][j].x[e]);
                wmma::store_matrix_sync(dst + (size_t)(m0 + wm * 64 + i * 16) * DD
                                            + col0 + wn * 64 + j * 16,
                                        chf, DD, wmma::mem_row_major);
            }
    }
}

// ===========================================================================
// Persistent attention with atomic work-stealing (fp16 WMMA) — R16 measured
// best (216.7us). num = expw @ EKV, den = expw @ EK;
// Yt = half(sigmoid(Qh) * cN/cD)  (bq pre-folded into Qh).
// Tile = 128(t) x 64(d) x batch; decode: d=tile&7, t=(tile>>3)&7, b=tile>>6.
// ===========================================================================
#define A_STAGE 18432   // halves per stage: Ws 128x72 + EK 64x72 + EKV 64x72
#define A_SMEM (2 * A_STAGE * 2)   // 73728 B
#define A_NT 2048

__global__ __launch_bounds__(128, 3)
void attnh(const __half* __restrict__ expw, const __half* __restrict__ EK,
           const __half* __restrict__ EKV, const __half* __restrict__ Qh,
           int* ctr, __half* __restrict__ Yt)
{
    extern __shared__ __half sh[];
    __shared__ int s_next;
    const int tid = threadIdx.x;
    const int wid = tid >> 5;
    const int wm = wid >> 1;          // 0..1 (64 t-rows)
    const int wn = wid & 1;           // 0..1 (32 d-cols)

    auto issue = [&](int t0, int d0, int b, int s0, int buf) {
        __half* Ws  = sh + buf * A_STAGE;
        __half* EKs = Ws + 128 * 72;
        __half* EVs = EKs + 64 * 72;
        const __half* ekp = EK  + (size_t)b * TT * DD + d0;
        const __half* evp = EKV + (size_t)b * TT * DD + d0;
#pragma unroll
        for (int i = 0; i < 8; i++) {          // Ws: 128x64 -> 1024 cp16
            const int f = tid + i * 128;
            const int row = f >> 3, c8 = f & 7;
            CP16(Ws + row * 72 + c8 * 8, expw + (size_t)(t0 + row) * TT + s0 + c8 * 8);
        }
#pragma unroll
        for (int i = 0; i < 4; i++) {          // EK/EKV: 64x64 -> 512 cp16 each
            const int f = tid + i * 128;
            const int row = f >> 3, c8 = f & 7;
            CP16(EKs + row * 72 + c8 * 8, ekp + (size_t)(s0 + row) * DD + c8 * 8);
            CP16(EVs + row * 72 + c8 * 8, evp + (size_t)(s0 + row) * DD + c8 * 8);
        }
        CP_COMMIT();
    };

    const int NC = TT / 64;   // 16
    if (tid == 0) s_next = atomicAdd(ctr, 1);
    __syncthreads();
    int tile = s_next;
    int buf = 0;
    if (tile < A_NT)
        issue(((tile >> 3) & 7) * 128, (tile & 7) * 64, tile >> 6, 0, buf);

    while (tile < A_NT) {
        const int d0 = (tile & 7) * 64;
        const int t0 = ((tile >> 3) & 7) * 128;
        const int b  = tile >> 6;

        wmma::fragment<wmma::accumulator, 16, 16, 16, float> cN[4][2], cD[4][2];
#pragma unroll
        for (int i = 0; i < 4; i++)
#pragma unroll
            for (int j = 0; j < 2; j++) {
                wmma::fill_fragment(cN[i][j], 0.0f);
                wmma::fill_fragment(cD[i][j], 0.0f);
            }

        for (int ch = 0; ch < NC; ch++) {
            CP_WAIT0();
            __syncthreads();   // also publishes s_next written at ch == NC-2
            const int ib = buf ^ 1;
            if (ch + 1 < NC) {
                issue(t0, d0, b, (ch + 1) * 64, ib);
            } else {
                const int nt = s_next;
                if (nt < A_NT)
                    issue(((nt >> 3) & 7) * 128, (nt & 7) * 64, nt >> 6, 0, ib);
            }
            if (ch == NC - 2 && tid == 0) s_next = atomicAdd(ctr, 1);

            const __half* Ws  = sh + buf * A_STAGE;
            const __half* EKs = Ws + 128 * 72;
            const __half* EVs = EKs + 64 * 72;
#pragma unroll
            for (int kk = 0; kk < 4; kk++) {
                wmma::fragment<wmma::matrix_a, 16, 16, 16, __half, wmma::row_major> a[4];
                wmma::fragment<wmma::matrix_b, 16, 16, 16, __half, wmma::row_major> bK[2], bV[2];
#pragma unroll
                for (int i = 0; i < 4; i++)
                    wmma::load_matrix_sync(a[i], Ws + (wm * 64 + i * 16) * 72 + kk * 16, 72);
#pragma unroll
                for (int j = 0; j < 2; j++) {
                    wmma::load_matrix_sync(bK[j], EKs + (kk * 16) * 72 + wn * 32 + j * 16, 72);
                    wmma::load_matrix_sync(bV[j], EVs + (kk * 16) * 72 + wn * 32 + j * 16, 72);
                }
#pragma unroll
                for (int i = 0; i < 4; i++)
#pragma unroll
                    for (int j = 0; j < 2; j++) {
                        wmma::mma_sync(cN[i][j], a[i], bV[j], cN[i][j]);
                        wmma::mma_sync(cD[i][j], a[i], bK[j], cD[i][j]);
                    }
            }
            buf ^= 1;
        }

        // Fragment-only epilogue — overlaps next-tile prefetch.
        wmma::fragment<wmma::accumulator, 16, 16, 16, __half> qf, yf;
#pragma unroll
        for (int i = 0; i < 4; i++)
#pragma unroll
            for (int j = 0; j < 2; j++) {
                const size_t tp = ((size_t)b * TT + t0 + wm * 64 + i * 16) * DD
                                + d0 + wn * 32 + j * 16;
                wmma::load_matrix_sync(qf, Qh + tp, DD, wmma::mem_row_major);
#pragma unroll
                for (int e = 0; e < qf.num_elements; e++) {
                    const float q = __half2float(qf.x[e]);
                    const float r = cN[i][j].x[e] / cD[i][j].x[e];
                    yf.x[e] = __float2half((1.f / (1.f + expf(-q))) * r);
                }
                wmma::store_matrix_sync(Yt + tp, yf, DD, wmma::mem_row_major);
            }
        tile = s_next;
    }
}

// ===========================================================================
// Fused batch-max + exp + bias-fold over half K/V (4 halves / thread)
// ===========================================================================
__global__ __launch_bounds__(128)
void kmax_ekv_kernel(const __half* __restrict__ Kh, const __half* __restrict__ Vh,
                     const float* __restrict__ bv,
                     __half* __restrict__ EK, __half* __restrict__ EKV)
{
    const int idx = (blockIdx.x * 128 + threadIdx.x) * 4;   // < TT*DD
    const float4 bvv = __ldg((const float4*)(bv + (idx & (DD - 1))));

    uint2 kvh[BB];
    __half2 m0 = __float2half2_rn(-65504.f), m1 = m0;
#pragma unroll
    for (int b = 0; b < BB; b++) {
        kvh[b] = *(const uint2*)(Kh + (size_t)b * TT * DD + idx);
        m0 = __hmax2(m0, *(const __half2*)&kvh[b].x);
        m1 = __hmax2(m1, *(const __half2*)&kvh[b].y);
    }
    const float2 mf0 = __half22float2(m0);
    const float2 mf1 = __half22float2(m1);
#pragma unroll
    for (int b = 0; b < BB; b++) {
        const size_t gi = (size_t)b * TT * DD + idx;
        uint2 vv = *(const uint2*)(Vh + gi);
        float2 k0 = __half22float2(*(const __half2*)&kvh[b].x);
        float2 k1 = __half22float2(*(const __half2*)&kvh[b].y);
        float2 v0 = __half22float2(*(const __half2*)&vv.x);
        float2 v1 = __half22float2(*(const __half2*)&vv.y);
        const float e0 = expf(k0.x - mf0.x);
        const float e1 = expf(k0.y - mf0.y);
        const float e2 = expf(k1.x - mf1.x);
        const float e3 = expf(k1.y - mf1.y);
        uint2 ek, ekv;
        *(__half2*)&ek.x  = __floats2half2_rn(e0, e1);
        *(__half2*)&ek.y  = __floats2half2_rn(e2, e3);
        *(__half2*)&ekv.x = __floats2half2_rn(e0 * (v0.x + bvv.x), e1 * (v0.y + bvv.y));
        *(__half2*)&ekv.y = __floats2half2_rn(e2 * (v1.x + bvv.z), e3 * (v1.y + bvv.w));
        *(uint2*)(EK + gi)  = ek;
        *(uint2*)(EKV + gi) = ekv;
    }
}

// ===========================================================================
// Merged prep: f2h(x) [blocks 0..16383], wconv [16384..17407],
// brep + counter reset [17408..17439], brep3 [17440..17535],
// expw rows [17536..18559]
// ===========================================================================
__global__ __launch_bounds__(256)
void prep_kernel(const float* __restrict__ x, __half* __restrict__ xh,
                 const float* __restrict__ Wk, const float* __restrict__ Wv,
                 const float* __restrict__ Wq, const float* __restrict__ Wo,
                 __half* __restrict__ W3h, __half* __restrict__ Woh,
                 const float* __restrict__ bo, float* __restrict__ brep,
                 const float* __restrict__ bq, float* __restrict__ brep3,
                 const float* __restrict__ w, __half* __restrict__ ew)
{
    const int blk = blockIdx.x;
    if (blk < 16384) {
        const size_t f = (size_t)blk * 256 + threadIdx.x;   // f4 index over x
        float4 v = ((const float4*)x)[f];
        __half2* d = (__half2*)(xh + f * 4);
        d[0] = __floats2half2_rn(v.x, v.y);
        d[1] = __floats2half2_rn(v.z, v.w);
    } else if (blk < 17408) {
        const int f = (blk - 16384) * 256 + threadIdx.x;    // f4 index < 4*65536
        const int per = DD * DD / 4;
        const float* src; __half* dst; int off;
        if (f < per)           { src = Wk; dst = W3h;            off = f; }
        else if (f < 2 * per)  { src = Wv; dst = W3h + DD * DD;  off = f - per; }
        else if (f < 3 * per)  { src = Wq; dst = W3h + 2*DD*DD;  off = f - 2 * per; }
        else                   { src = Wo; dst = Woh;            off = f - 3 * per; }
        float4 v = ((const float4*)src)[off];
        __half2* d = (__half2*)(dst + (size_t)off * 4);
        d[0] = __floats2half2_rn(v.x, v.y);
        d[1] = __floats2half2_rn(v.z, v.w);
    } else if (blk < 17440) {
        const int idx = (blk - 17408) * 256 + threadIdx.x;  // < 16*DD
        brep[idx] = bo[idx & (DD - 1)];
        if (blk == 17408 && threadIdx.x < 4) g_ctr[threadIdx.x] = 0;
    } else if (blk < 17536) {
        const int idx = (blk - 17440) * 256 + threadIdx.x;  // < 16*1536
        const int col = idx % (3 * DD);
        brep3[idx] = (col >= 2 * DD) ? bq[col - 2 * DD] : 0.0f;
    } else {
        const int t = blk - 17536;
        const float* row = w + (size_t)t * TT;
        float m = -INFINITY;
        for (int i = threadIdx.x; i < TT; i += 256) m = fmaxf(m, row[i]);
#pragma unroll
        for (int o = 16; o > 0; o >>= 1)
            m = fmaxf(m, __shfl_xor_sync(0xffffffffu, m, o));
        __shared__ float warpmax[8];
        __shared__ float rowmax;
        if ((threadIdx.x & 31) == 0) warpmax[threadIdx.x >> 5] = m;
        __syncthreads();
        if (threadIdx.x == 0) {
            float mm = warpmax[0];
#pragma unroll
            for (int i = 1; i < 8; i++) mm = fmaxf(mm, warpmax[i]);
            rowmax = mm;
        }
        __syncthreads();
        const float rm = rowmax;
        for (int i = threadIdx.x; i < TT; i += 256)
            ew[(size_t)t * TT + i] = __float2half(expf(row[i] - rm));
    }
}

// ===========================================================================
extern "C" void kernel_launch(void* const* d_in, const int* in_sizes, int n_in,
                              void* d_out, int out_size)
{
    const float* x    = (const float*)d_in[0];
    const float* Wk_w = (const float*)d_in[1];
    // Wk_b unused: K bias cancels inside exp(K - max_b K)
    const float* Wv_w = (const float*)d_in[3];
    const float* Wv_b = (const float*)d_in[4];
    const float* Wq_w = (const float*)d_in[5];
    const float* Wq_b = (const float*)d_in[6];
    const float* w    = (const float*)d_in[7];
    const float* Wo_w = (const float*)d_in[8];
    const float* Wo_b = (const float*)d_in[9];
    float* out = (float*)d_out;

    float *pbrep, *pbrep3;
    int *pctr;
    __half *pKh, *pVh, *pQh, *pxh, *pW3h, *pWoh, *pexpwh, *pEKh, *pEKVh, *pYth;
    cudaGetSymbolAddress((void**)&pbrep, g_brep);
    cudaGetSymbolAddress((void**)&pbrep3, g_brep3);
    cudaGetSymbolAddress((void**)&pctr, g_ctr);
    cudaGetSymbolAddress((void**)&pKh, g_Kh);
    cudaGetSymbolAddress((void**)&pVh, g_Vh);
    cudaGetSymbolAddress((void**)&pQh, g_Qh);
    cudaGetSymbolAddress((void**)&pxh, g_xh);
    cudaGetSymbolAddress((void**)&pW3h, g_W3h);
    cudaGetSymbolAddress((void**)&pWoh, g_Woh);
    cudaGetSymbolAddress((void**)&pexpwh, g_expwh);
    cudaGetSymbolAddress((void**)&pEKh, g_EKh);
    cudaGetSymbolAddress((void**)&pEKVh, g_EKVh);
    cudaGetSymbolAddress((void**)&pYth, g_Yth);

    cudaFuncSetAttribute(linh,  cudaFuncAttributeMaxDynamicSharedMemorySize, L_SMEM);
    cudaFuncSetAttribute(attnh, cudaFuncAttributeMaxDynamicSharedMemorySize, A_SMEM);

    // #1 prep (f2h + wconv + brep/brep3 + counter reset + expw)
    prep_kernel<<<18560, 256>>>(x, pxh, Wk_w, Wv_w, Wq_w, Wo_w, pW3h, pWoh,
                                Wo_b, pbrep, Wq_b, pbrep3, w, pexpwh);

    // #2 fused K/V/Q linear (half out, bq folded into Q): grid (12, 256)
    linh<<<dim3(12, MM / 128), 128, L_SMEM>>>(pxh, pW3h, pbrep3, 3 * DD,
                                              pKh, pVh, pQh, nullptr);

    // #3 fused batch-max + exp (+ V bias)
    kmax_ekv_kernel<<<(TT * DD / 4) / 128, 128>>>(pKh, pVh, Wv_b, pEKh, pEKVh);

    // #4 attention (persistent + stealing, fragment epilogue)
    attnh<<<NPERS, 128, A_SMEM>>>(pexpwh, pEKh, pEKVh, pQh, pctr + 1, pYth);

    // #5 final linear with Wo bias (fp32 out): grid (4, 256)
    linh<<<dim3(4, MM / 128), 128, L_SMEM>>>(pYth, pWoh, pbrep, DD,
                                             nullptr, nullptr, nullptr, out);
}